// round 9
// baseline (speedup 1.0000x reference)
#include <cuda_runtime.h>
#include <math.h>

#define B_    32
#define H_    6
#define W_    2400
#define C_    64
#define OV_   4
#define G_    3
#define NVQ_  6
#define K_    1024
#define D_    8
#define FIX_  384
#define GD_   512
#define T_    600
#define NPG   (B_*T_)              // 19200
#define NPTS  (G_*NPG)             // 57600
#define ZQ_SIZE  (B_*H_*W_*C_)     // 29491200
#define IDX_SIZE (B_*NVQ_*G_*T_)   // 345600
#define RVQ_BLOCKS 1800            // 32 points per block, 32 threads

__device__ float g_en2s[G_*NVQ_*K_*D_];  // split layout [jl][q][s][pos]
__device__ float g_zd [G_*NPG*D_];
__device__ float g_zqd[G_*NPG*D_];
__device__ float g_partial[RVQ_BLOCKS];

// ---------------------------------------------------------------------------
// K0: dummy launch to shift the ncu capture window onto k_rvq.
// ---------------------------------------------------------------------------
__global__ void k_dummy() {
    if (threadIdx.x == 0) g_partial[0] = 0.f;   // overwritten by k_rvq later
}

// ---------------------------------------------------------------------------
// K1: normalize codebook rows, split layout:
// g_en2s[gi*8192 + jl*64 + (d>>1)*16 + s*4 + (d&1)*2 + half]
// ---------------------------------------------------------------------------
__global__ void k_norm(const float* __restrict__ cb) {
    int r = blockIdx.x * blockDim.x + threadIdx.x;
    if (r >= G_*NVQ_*K_) return;
    const float* src = cb + (size_t)r * D_;
    float v[8]; float ss = 0.f;
#pragma unroll
    for (int d = 0; d < 8; d++) { v[d] = src[d]; ss = fmaf(v[d], v[d], ss); }
    float inv = 1.0f / fmaxf(sqrtf(ss), 1e-12f);
    int gi = r >> 10, k = r & 1023;
    int s = k >> 8, jl = (k & 255) >> 1, half = k & 1;
    float* d2 = g_en2s + (size_t)gi*(K_*D_) + jl*64 + s*4 + half;
#pragma unroll
    for (int d = 0; d < 8; d++)
        d2[(d >> 1)*16 + (d & 1)*2] = v[d] * inv;
}

// ---------------------------------------------------------------------------
// K2: pre_process fused with proj_down (paired-h STS.64 staging).
// ---------------------------------------------------------------------------
#define SZ_STRIDE 1540
#define PD_STRIDE 520
#define K2_SMEM   ((8*SZ_STRIDE + 24*PD_STRIDE) * 4)

__global__ void k_down(const float* __restrict__ ze, const float* __restrict__ pd) {
    extern __shared__ float sm[];
    float* sZ  = sm;
    float* sPD = sm + 8*SZ_STRIDE;
    int bid  = blockIdx.x;
    int b    = bid / (T_/8);
    int tblk = bid % (T_/8);
    int t0   = tblk * 8;
    int w0   = t0 * 4;
    int tid  = threadIdx.x;

    for (int idx = tid; idx < G_*D_*GD_; idx += 256) {
        int gd = idx >> 9, j = idx & 511;
        sPD[gd*PD_STRIDE + j] = pd[idx];
    }
#pragma unroll
    for (int hp = 0; hp < 3; hp++) {
        const float* s0 = ze + ((size_t)(b*H_ + 2*hp    )*W_ + w0) * C_;
        const float* s1 = ze + ((size_t)(b*H_ + 2*hp + 1)*W_ + w0) * C_;
        for (int e = tid; e < 32*64; e += 256) {
            float v0 = s0[e], v1 = s1[e];
            int wl = e >> 6, c = e & 63;
            int tl = wl >> 2, o = wl & 3;
            *(float2*)(sZ + tl*SZ_STRIDE + o*FIX_ + c*6 + 2*hp) = make_float2(v0, v1);
        }
    }
    __syncthreads();

    if (tid < 192) {
        int gd = tid >> 3;
        int tl = tid & 7;
        int g  = gd >> 3, d = gd & 7;
        const float4* zr = (const float4*)(sZ + tl*SZ_STRIDE + g*GD_);
        const float4* pr = (const float4*)(sPD + gd*PD_STRIDE);
        float a0 = 0.f, a1 = 0.f, a2 = 0.f, a3 = 0.f;
#pragma unroll 8
        for (int j = 0; j < 128; j += 2) {
            float4 z0 = zr[j],   p0 = pr[j];
            float4 z1 = zr[j+1], p1 = pr[j+1];
            a0 = fmaf(z0.x, p0.x, a0); a1 = fmaf(z0.y, p0.y, a1);
            a2 = fmaf(z0.z, p0.z, a2); a3 = fmaf(z0.w, p0.w, a3);
            a0 = fmaf(z1.x, p1.x, a0); a1 = fmaf(z1.y, p1.y, a1);
            a2 = fmaf(z1.z, p1.z, a2); a3 = fmaf(z1.w, p1.w, a3);
        }
        g_zd[((size_t)g*NPG + b*T_ + t0 + tl)*D_ + d] = (a0 + a1) + (a2 + a3);
    }
}

// ---------------------------------------------------------------------------
// K3: residual VQ. Block = ONE warp = 8 point-slots x 4 k-splits,
// 4 points per thread -> 32 points/block, 1800 blocks (work-stealing
// smooths the 12.16-blocks/SM tail). Warp-level syncs only.
// ---------------------------------------------------------------------------
__device__ __forceinline__ int combine4(float best, int bk) {
    unsigned bits = __float_as_uint(best);
    unsigned su = bits ^ (unsigned)(((int)bits >> 31) | 0x80000000);
    unsigned long long key = ((unsigned long long)su << 10) | (unsigned)(1023 - bk);
    unsigned long long o = __shfl_xor_sync(0xffffffffu, key, 1);
    key = (o > key) ? o : key;
    o = __shfl_xor_sync(0xffffffffu, key, 2);
    key = (o > key) ? o : key;
    return 1023 - (int)(key & 1023u);
}

__global__ void __launch_bounds__(32) k_rvq(float* __restrict__ out_codes) {
    __shared__ float sE[K_*D_];   // 32 KB
    int bid  = blockIdx.x;
    int g    = bid / (RVQ_BLOCKS/G_);      // 600 blocks per group
    int lb   = bid % (RVQ_BLOCKS/G_);
    int tid  = threadIdx.x;
    int slot = tid >> 2;                   // 0..7
    int s    = tid & 3;                    // split
    int pl0  = lb*32 + slot*4;
    int p0   = g*NPG + pl0;

    unsigned long long r2[4][8];
    {
        const float4* zd4 = (const float4*)g_zd;
#pragma unroll
        for (int m = 0; m < 4; m++) {
            float4 lo = zd4[(size_t)(p0+m)*2], hi = zd4[(size_t)(p0+m)*2+1];
            float rv[8] = { lo.x, lo.y, lo.z, lo.w, hi.x, hi.y, hi.z, hi.w };
#pragma unroll
            for (int d = 0; d < 8; d++)
                asm("mov.b64 %0, {%1, %1};" : "=l"(r2[m][d]) : "f"(rv[d]));
        }
    }
    int ofs[4];
#pragma unroll
    for (int m = 0; m < 4; m++) {
        int pl = pl0 + m;
        int b = pl / T_, t = pl - b*T_;
        ofs[m] = (b*NVQ_*G_ + g)*T_ + t;
    }

    float sse = 0.f;

    for (int i = 0; i < NVQ_; i++) {
        __syncwarp();
        {
            const float4* src = (const float4*)(g_en2s + (size_t)(g*NVQ_ + i)*(K_*D_));
            float4* dst = (float4*)sE;
#pragma unroll
            for (int j = 0; j < 64; j++) dst[tid + j*32] = src[tid + j*32];
        }
        __syncwarp();

        const ulonglong2* e2 = (const ulonglong2*)sE;
        float best[4] = { -3.0e38f, -3.0e38f, -3.0e38f, -3.0e38f };
        int   bj[4]   = { 0, 0, 0, 0 };
#pragma unroll 2
        for (int j = 0; j < 128; j++) {
            int base = j*16 + s;
            ulonglong2 c0 = e2[base];
            ulonglong2 c1 = e2[base + 4];
            ulonglong2 c2 = e2[base + 8];
            ulonglong2 c3 = e2[base + 12];
#define SIM(mm, ACC) \
            asm("mul.rn.f32x2 %0, %1, %2;"     : "=l"(ACC) : "l"(r2[mm][0]), "l"(c0.x)); \
            asm("fma.rn.f32x2 %0, %1, %2, %0;" : "+l"(ACC) : "l"(r2[mm][1]), "l"(c0.y)); \
            asm("fma.rn.f32x2 %0, %1, %2, %0;" : "+l"(ACC) : "l"(r2[mm][2]), "l"(c1.x)); \
            asm("fma.rn.f32x2 %0, %1, %2, %0;" : "+l"(ACC) : "l"(r2[mm][3]), "l"(c1.y)); \
            asm("fma.rn.f32x2 %0, %1, %2, %0;" : "+l"(ACC) : "l"(r2[mm][4]), "l"(c2.x)); \
            asm("fma.rn.f32x2 %0, %1, %2, %0;" : "+l"(ACC) : "l"(r2[mm][5]), "l"(c2.y)); \
            asm("fma.rn.f32x2 %0, %1, %2, %0;" : "+l"(ACC) : "l"(r2[mm][6]), "l"(c3.x)); \
            asm("fma.rn.f32x2 %0, %1, %2, %0;" : "+l"(ACC) : "l"(r2[mm][7]), "l"(c3.y));
            unsigned long long a0, a1, a2, a3;
            SIM(0, a0) SIM(1, a1) SIM(2, a2) SIM(3, a3)
            float lo, hi, m;
#define CMP(mm, ACC) \
            asm("mov.b64 {%0, %1}, %2;" : "=f"(lo), "=f"(hi) : "l"(ACC)); \
            m = fmaxf(lo, hi); \
            if (m > best[mm]) { best[mm] = m; bj[mm] = j; }
            CMP(0, a0) CMP(1, a1) CMP(2, a2) CMP(3, a3)
#undef CMP
        }

        // resolve even/odd by recomputing the winning pair (same op order)
        int kk[4];
#pragma unroll
        for (int m = 0; m < 4; m++) {
            int base = bj[m]*16 + s;
            ulonglong2 c0 = e2[base];
            ulonglong2 c1 = e2[base + 4];
            ulonglong2 c2 = e2[base + 8];
            ulonglong2 c3 = e2[base + 12];
            unsigned long long a;
            switch (m) {
                case 0: { SIM(0, a) } break;
                case 1: { SIM(1, a) } break;
                case 2: { SIM(2, a) } break;
                default:{ SIM(3, a) } break;
            }
            float lo, hi;
            asm("mov.b64 {%0, %1}, %2;" : "=f"(lo), "=f"(hi) : "l"(a));
            int kc = s*256 + 2*bj[m] + ((hi > lo) ? 1 : 0);
            kk[m] = combine4(best[m], kc);
        }
#undef SIM

        // gather chosen codeword from smem + update residual
#pragma unroll
        for (int m = 0; m < 4; m++) {
            int k = kk[m];
            int base = ((k & 255) >> 1)*64 + ((k >> 8) << 2) + (k & 1);
            float ss = 0.f;
#pragma unroll
            for (int d = 0; d < 8; d++) {
                float ev = sE[base + (d >> 1)*16 + (d & 1)*2];
                float rlo;
                asm("mov.b64 {%0, _}, %1;" : "=f"(rlo) : "l"(r2[m][d]));
                float rn = rlo - ev;
                asm("mov.b64 %0, {%1, %1};" : "=l"(r2[m][d]) : "f"(rn));
                ss = fmaf(rn, rn, ss);
            }
            sse += ss;
        }
        if (s == 0) {
            float* oc = out_codes + (size_t)i*(G_*T_);
#pragma unroll
            for (int m = 0; m < 4; m++) oc[ofs[m]] = (float)kk[m];
        }
    }

    // q = zd - r_final; write zqd
    if (s == 0) {
        const float4* zd4 = (const float4*)g_zd;
        float4* zq4 = (float4*)g_zqd;
#pragma unroll
        for (int m = 0; m < 4; m++) {
            float4 lo = zd4[(size_t)(p0+m)*2], hi = zd4[(size_t)(p0+m)*2+1];
            float zv[8] = { lo.x, lo.y, lo.z, lo.w, hi.x, hi.y, hi.z, hi.w };
            float qv[8];
#pragma unroll
            for (int d = 0; d < 8; d++) {
                float rlo;
                asm("mov.b64 {%0, _}, %1;" : "=f"(rlo) : "l"(r2[m][d]));
                qv[d] = zv[d] - rlo;
            }
            zq4[(size_t)(p0+m)*2]   = make_float4(qv[0], qv[1], qv[2], qv[3]);
            zq4[(size_t)(p0+m)*2+1] = make_float4(qv[4], qv[5], qv[6], qv[7]);
        }
    }

    // deterministic warp reduction of sse (count each point once: s==0)
    float c = (s == 0) ? sse : 0.f;
#pragma unroll
    for (int off = 16; off > 0; off >>= 1)
        c += __shfl_down_sync(0xffffffffu, c, off);
    if (tid == 0) g_partial[bid] = c;
}

// ---------------------------------------------------------------------------
// K4: proj_up fused with post_process (R5 version).
// ---------------------------------------------------------------------------
#define TT 25
__global__ void __launch_bounds__(256) k_up(const float* __restrict__ pu, float* __restrict__ out) {
    __shared__ float sZ[G_*TT*D_];
    int bid  = blockIdx.x;
    int b    = bid / (T_/TT);
    int tile = bid % (T_/TT);
    int t0   = tile * TT;
    int tid  = threadIdx.x;

    for (int idx = tid; idx < G_*TT*D_; idx += 256) {
        int g  = idx / (TT*D_);
        int rr = idx % (TT*D_);
        sZ[idx] = g_zqd[((size_t)g*NPG + b*T_ + t0)*D_ + rr];
    }
    __syncthreads();

    int wid = tid >> 5, lane = tid & 31;
    for (int task = wid; task < 48; task += 8) {
        int o   = task / 12;
        int rem = task % 12;
        int h   = rem >> 1;
        int ch  = rem & 1;
        int c   = ch*32 + lane;
        int pp  = o*FIX_ + c*6 + h;
        int g   = pp >> 9;
        const float4* pu4 = (const float4*)pu + (size_t)pp*2;
        float4 pl = __ldg(pu4), ph = __ldg(pu4 + 1);
        float* op = out + ((size_t)(b*H_ + h)*W_ + 4*t0 + o)*C_ + c;
        const float4* zb = (const float4*)(sZ + g*(TT*D_));
#pragma unroll 5
        for (int tl = 0; tl < TT; tl++) {
            float4 zl = zb[tl*2], zh = zb[tl*2 + 1];
            float s0 = zl.x*pl.x, s1 = zl.y*pl.y;
            s0 = fmaf(zl.z, pl.z, s0); s1 = fmaf(zl.w, pl.w, s1);
            s0 = fmaf(zh.x, ph.x, s0); s1 = fmaf(zh.y, ph.y, s1);
            s0 = fmaf(zh.z, ph.z, s0); s1 = fmaf(zh.w, ph.w, s1);
            op[(size_t)tl*4*C_] = s0 + s1;
        }
    }
}

// ---------------------------------------------------------------------------
// K5: final deterministic loss reduction over 1800 partials.
// ---------------------------------------------------------------------------
__global__ void k_final(float* __restrict__ d_out) {
    __shared__ float s[512];
    int tid = threadIdx.x;
    float v = 0.f;
    for (int idx = tid; idx < RVQ_BLOCKS; idx += 512) v += g_partial[idx];
    s[tid] = v; __syncthreads();
    for (int off = 256; off > 0; off >>= 1) {
        if (tid < off) s[tid] += s[tid + off];
        __syncthreads();
    }
    if (tid == 0) {
        float loss = s[0] / (float)(G_ * B_ * T_ * D_);
        d_out[ZQ_SIZE + IDX_SIZE]     = loss;
        d_out[ZQ_SIZE + IDX_SIZE + 1] = loss;
    }
}

// ---------------------------------------------------------------------------
extern "C" void kernel_launch(void* const* d_in, const int* in_sizes, int n_in,
                              void* d_out, int out_size) {
    const float* z_e = (const float*)d_in[0];
    const float* pd  = (const float*)d_in[1];
    const float* pu  = (const float*)d_in[2];
    const float* cb  = (const float*)d_in[3];
    float* out = (float*)d_out;

    cudaFuncSetAttribute(k_down, cudaFuncAttributeMaxDynamicSharedMemorySize, K2_SMEM);

    k_dummy<<<1, 32>>>();   // shifts ncu capture onto k_rvq
    k_norm<<<(G_*NVQ_*K_ + 255)/256, 256>>>(cb);
    k_down<<<B_*(T_/8), 256, K2_SMEM>>>(z_e, pd);
    k_rvq<<<RVQ_BLOCKS, 32>>>(out + ZQ_SIZE);
    k_up<<<B_*(T_/TT), 256>>>(pu, out);
    k_final<<<1, 512>>>(out);
}

// round 10
// speedup vs baseline: 1.6408x; 1.6408x over previous
#include <cuda_runtime.h>
#include <math.h>

#define B_    32
#define H_    6
#define W_    2400
#define C_    64
#define OV_   4
#define G_    3
#define NVQ_  6
#define K_    1024
#define D_    8
#define FIX_  384
#define GD_   512
#define T_    600
#define NPG   (B_*T_)              // 19200
#define NPTS  (G_*NPG)             // 57600
#define ZQ_SIZE  (B_*H_*W_*C_)     // 29491200
#define IDX_SIZE (B_*NVQ_*G_*T_)   // 345600
#define RVQ_BLOCKS 1800            // 32 points per block, 64 threads, 8 splits

__device__ float g_en8s[G_*NVQ_*K_*D_];  // 8-split layout
__device__ float g_zd [G_*NPG*D_];
__device__ float g_zqd[G_*NPG*D_];
__device__ float g_partial[RVQ_BLOCKS];

// ---------------------------------------------------------------------------
// K0: dummy launch to keep the ncu capture window on k_rvq.
// ---------------------------------------------------------------------------
__global__ void k_dummy() {
    if (threadIdx.x == 0) g_partial[0] = 0.f;
}

// ---------------------------------------------------------------------------
// K1: normalize codebook rows, 8-split layout:
// k: s = k>>7 (0..7), jl = (k&127)>>1 (0..63), half = k&1
// float index = jl*128 + (d>>1)*32 + s*4 + (d&1)*2 + half
// (row jl = 512B: unit16B = c*8 + s, c = d-pair)
// ---------------------------------------------------------------------------
__global__ void k_norm(const float* __restrict__ cb) {
    int r = blockIdx.x * blockDim.x + threadIdx.x;
    if (r >= G_*NVQ_*K_) return;
    const float* src = cb + (size_t)r * D_;
    float v[8]; float ss = 0.f;
#pragma unroll
    for (int d = 0; d < 8; d++) { v[d] = src[d]; ss = fmaf(v[d], v[d], ss); }
    float inv = 1.0f / fmaxf(sqrtf(ss), 1e-12f);
    int gi = r >> 10, k = r & 1023;
    int s = k >> 7, jl = (k & 127) >> 1, half = k & 1;
    float* d2 = g_en8s + (size_t)gi*(K_*D_) + jl*128 + s*4 + half;
#pragma unroll
    for (int d = 0; d < 8; d++)
        d2[(d >> 1)*32 + (d & 1)*2] = v[d] * inv;
}

// ---------------------------------------------------------------------------
// K2: pre_process fused with proj_down (paired-h STS.64 staging).
// ---------------------------------------------------------------------------
#define SZ_STRIDE 1540
#define PD_STRIDE 520
#define K2_SMEM   ((8*SZ_STRIDE + 24*PD_STRIDE) * 4)

__global__ void k_down(const float* __restrict__ ze, const float* __restrict__ pd) {
    extern __shared__ float sm[];
    float* sZ  = sm;
    float* sPD = sm + 8*SZ_STRIDE;
    int bid  = blockIdx.x;
    int b    = bid / (T_/8);
    int tblk = bid % (T_/8);
    int t0   = tblk * 8;
    int w0   = t0 * 4;
    int tid  = threadIdx.x;

    for (int idx = tid; idx < G_*D_*GD_; idx += 256) {
        int gd = idx >> 9, j = idx & 511;
        sPD[gd*PD_STRIDE + j] = pd[idx];
    }
#pragma unroll
    for (int hp = 0; hp < 3; hp++) {
        const float* s0 = ze + ((size_t)(b*H_ + 2*hp    )*W_ + w0) * C_;
        const float* s1 = ze + ((size_t)(b*H_ + 2*hp + 1)*W_ + w0) * C_;
        for (int e = tid; e < 32*64; e += 256) {
            float v0 = s0[e], v1 = s1[e];
            int wl = e >> 6, c = e & 63;
            int tl = wl >> 2, o = wl & 3;
            *(float2*)(sZ + tl*SZ_STRIDE + o*FIX_ + c*6 + 2*hp) = make_float2(v0, v1);
        }
    }
    __syncthreads();

    if (tid < 192) {
        int gd = tid >> 3;
        int tl = tid & 7;
        int g  = gd >> 3, d = gd & 7;
        const float4* zr = (const float4*)(sZ + tl*SZ_STRIDE + g*GD_);
        const float4* pr = (const float4*)(sPD + gd*PD_STRIDE);
        float a0 = 0.f, a1 = 0.f, a2 = 0.f, a3 = 0.f;
#pragma unroll 8
        for (int j = 0; j < 128; j += 2) {
            float4 z0 = zr[j],   p0 = pr[j];
            float4 z1 = zr[j+1], p1 = pr[j+1];
            a0 = fmaf(z0.x, p0.x, a0); a1 = fmaf(z0.y, p0.y, a1);
            a2 = fmaf(z0.z, p0.z, a2); a3 = fmaf(z0.w, p0.w, a3);
            a0 = fmaf(z1.x, p1.x, a0); a1 = fmaf(z1.y, p1.y, a1);
            a2 = fmaf(z1.z, p1.z, a2); a3 = fmaf(z1.w, p1.w, a3);
        }
        g_zd[((size_t)g*NPG + b*T_ + t0 + tl)*D_ + d] = (a0 + a1) + (a2 + a3);
    }
}

// ---------------------------------------------------------------------------
// K3: residual VQ. 64 thr = 8 slots x 8 splits, 4 pts/thread, 32 pts/block,
// 1800 blocks (7 resident/SM via smem -> 14 warps/SM with work-stealing).
// Inline parity tracking (no dynamic indexing -> no spills).
// ---------------------------------------------------------------------------
__device__ __forceinline__ int combine8(float best, int bk) {
    unsigned bits = __float_as_uint(best);
    unsigned su = bits ^ (unsigned)(((int)bits >> 31) | 0x80000000);
    unsigned long long key = ((unsigned long long)su << 10) | (unsigned)(1023 - bk);
    unsigned long long o = __shfl_xor_sync(0xffffffffu, key, 1);
    key = (o > key) ? o : key;
    o = __shfl_xor_sync(0xffffffffu, key, 2);
    key = (o > key) ? o : key;
    o = __shfl_xor_sync(0xffffffffu, key, 4);
    key = (o > key) ? o : key;
    return 1023 - (int)(key & 1023u);
}

__global__ void __launch_bounds__(64, 7) k_rvq(float* __restrict__ out_codes) {
    __shared__ float sE[K_*D_];   // 32 KB
    __shared__ float sWarp[2];
    int bid  = blockIdx.x;
    int g    = bid / (RVQ_BLOCKS/G_);      // 600 blocks per group
    int lb   = bid % (RVQ_BLOCKS/G_);
    int tid  = threadIdx.x;
    int slot = tid >> 3;                   // 0..7
    int s    = tid & 7;                    // split 0..7
    int pl0  = lb*32 + slot*4;
    int p0   = g*NPG + pl0;

    unsigned long long r2[4][8];
    {
        const float4* zd4 = (const float4*)g_zd;
#pragma unroll
        for (int m = 0; m < 4; m++) {
            float4 lo = zd4[(size_t)(p0+m)*2], hi = zd4[(size_t)(p0+m)*2+1];
            float rv[8] = { lo.x, lo.y, lo.z, lo.w, hi.x, hi.y, hi.z, hi.w };
#pragma unroll
            for (int d = 0; d < 8; d++)
                asm("mov.b64 %0, {%1, %1};" : "=l"(r2[m][d]) : "f"(rv[d]));
        }
    }
    int ofs[4];
#pragma unroll
    for (int m = 0; m < 4; m++) {
        int pl = pl0 + m;
        int b = pl / T_, t = pl - b*T_;
        ofs[m] = (b*NVQ_*G_ + g)*T_ + t;
    }

    float sse = 0.f;

    for (int i = 0; i < NVQ_; i++) {
        __syncthreads();
        {
            const float4* src = (const float4*)(g_en8s + (size_t)(g*NVQ_ + i)*(K_*D_));
            float4* dst = (float4*)sE;
#pragma unroll
            for (int j = 0; j < 32; j++) dst[tid + j*64] = src[tid + j*64];
        }
        __syncthreads();

        const ulonglong2* e2 = (const ulonglong2*)sE;
        float best0 = -3.0e38f, best1 = -3.0e38f, best2v = -3.0e38f, best3 = -3.0e38f;
        int bk0 = 0, bk1 = 0, bk2 = 0, bk3 = 0;
#pragma unroll 2
        for (int j = 0; j < 64; j++) {
            int base = j*32 + s;              // row = 32 units of 16B
            ulonglong2 c0 = e2[base];
            ulonglong2 c1 = e2[base + 8];
            ulonglong2 c2 = e2[base + 16];
            ulonglong2 c3 = e2[base + 24];
#define SIM(mm, ACC) \
            asm("mul.rn.f32x2 %0, %1, %2;"     : "=l"(ACC) : "l"(r2[mm][0]), "l"(c0.x)); \
            asm("fma.rn.f32x2 %0, %1, %2, %0;" : "+l"(ACC) : "l"(r2[mm][1]), "l"(c0.y)); \
            asm("fma.rn.f32x2 %0, %1, %2, %0;" : "+l"(ACC) : "l"(r2[mm][2]), "l"(c1.x)); \
            asm("fma.rn.f32x2 %0, %1, %2, %0;" : "+l"(ACC) : "l"(r2[mm][3]), "l"(c1.y)); \
            asm("fma.rn.f32x2 %0, %1, %2, %0;" : "+l"(ACC) : "l"(r2[mm][4]), "l"(c2.x)); \
            asm("fma.rn.f32x2 %0, %1, %2, %0;" : "+l"(ACC) : "l"(r2[mm][5]), "l"(c2.y)); \
            asm("fma.rn.f32x2 %0, %1, %2, %0;" : "+l"(ACC) : "l"(r2[mm][6]), "l"(c3.x)); \
            asm("fma.rn.f32x2 %0, %1, %2, %0;" : "+l"(ACC) : "l"(r2[mm][7]), "l"(c3.y));
            unsigned long long a0, a1, a2, a3;
            SIM(0, a0) SIM(1, a1) SIM(2, a2) SIM(3, a3)
#undef SIM
            float lo, hi, m;
            int cand;
            asm("mov.b64 {%0, %1}, %2;" : "=f"(lo), "=f"(hi) : "l"(a0));
            m = fmaxf(lo, hi); cand = 2*j + ((hi > lo) ? 1 : 0);
            if (m > best0) { best0 = m; bk0 = cand; }
            asm("mov.b64 {%0, %1}, %2;" : "=f"(lo), "=f"(hi) : "l"(a1));
            m = fmaxf(lo, hi); cand = 2*j + ((hi > lo) ? 1 : 0);
            if (m > best1) { best1 = m; bk1 = cand; }
            asm("mov.b64 {%0, %1}, %2;" : "=f"(lo), "=f"(hi) : "l"(a2));
            m = fmaxf(lo, hi); cand = 2*j + ((hi > lo) ? 1 : 0);
            if (m > best2v) { best2v = m; bk2 = cand; }
            asm("mov.b64 {%0, %1}, %2;" : "=f"(lo), "=f"(hi) : "l"(a3));
            m = fmaxf(lo, hi); cand = 2*j + ((hi > lo) ? 1 : 0);
            if (m > best3) { best3 = m; bk3 = cand; }
        }
        int kk0 = combine8(best0, s*128 + bk0);
        int kk1 = combine8(best1, s*128 + bk1);
        int kk2 = combine8(best2v, s*128 + bk2);
        int kk3 = combine8(best3, s*128 + bk3);

        // gather chosen codeword from smem + update residual (+sse)
#define UPD(mm, KVAL) { \
            int k = (KVAL); \
            int base = ((k & 127) >> 1)*128 + ((k >> 7) << 2) + (k & 1); \
            float ss = 0.f; \
            _Pragma("unroll") \
            for (int d = 0; d < 8; d++) { \
                float ev = sE[base + (d >> 1)*32 + (d & 1)*2]; \
                float rlo; \
                asm("mov.b64 {%0, _}, %1;" : "=f"(rlo) : "l"(r2[mm][d])); \
                float rn = rlo - ev; \
                asm("mov.b64 %0, {%1, %1};" : "=l"(r2[mm][d]) : "f"(rn)); \
                ss = fmaf(rn, rn, ss); \
            } \
            sse += ss; }
        UPD(0, kk0) UPD(1, kk1) UPD(2, kk2) UPD(3, kk3)
#undef UPD

        if (s == 0) {
            float* oc = out_codes + (size_t)i*(G_*T_);
            oc[ofs[0]] = (float)kk0;
            oc[ofs[1]] = (float)kk1;
            oc[ofs[2]] = (float)kk2;
            oc[ofs[3]] = (float)kk3;
        }
    }

    // q = zd - r_final; write zqd
    if (s == 0) {
        const float4* zd4 = (const float4*)g_zd;
        float4* zq4 = (float4*)g_zqd;
#pragma unroll
        for (int m = 0; m < 4; m++) {
            float4 lo = zd4[(size_t)(p0+m)*2], hi = zd4[(size_t)(p0+m)*2+1];
            float zv[8] = { lo.x, lo.y, lo.z, lo.w, hi.x, hi.y, hi.z, hi.w };
            float qv[8];
#pragma unroll
            for (int d = 0; d < 8; d++) {
                float rlo;
                asm("mov.b64 {%0, _}, %1;" : "=f"(rlo) : "l"(r2[m][d]));
                qv[d] = zv[d] - rlo;
            }
            zq4[(size_t)(p0+m)*2]   = make_float4(qv[0], qv[1], qv[2], qv[3]);
            zq4[(size_t)(p0+m)*2+1] = make_float4(qv[4], qv[5], qv[6], qv[7]);
        }
    }

    float c = (s == 0) ? sse : 0.f;
#pragma unroll
    for (int off = 16; off > 0; off >>= 1)
        c += __shfl_down_sync(0xffffffffu, c, off);
    int lane = tid & 31, wid = tid >> 5;
    if (lane == 0) sWarp[wid] = c;
    __syncthreads();
    if (tid == 0) g_partial[bid] = sWarp[0] + sWarp[1];
}

// ---------------------------------------------------------------------------
// K4: proj_up fused with post_process (R5 version).
// ---------------------------------------------------------------------------
#define TT 25
__global__ void __launch_bounds__(256) k_up(const float* __restrict__ pu, float* __restrict__ out) {
    __shared__ float sZ[G_*TT*D_];
    int bid  = blockIdx.x;
    int b    = bid / (T_/TT);
    int tile = bid % (T_/TT);
    int t0   = tile * TT;
    int tid  = threadIdx.x;

    for (int idx = tid; idx < G_*TT*D_; idx += 256) {
        int g  = idx / (TT*D_);
        int rr = idx % (TT*D_);
        sZ[idx] = g_zqd[((size_t)g*NPG + b*T_ + t0)*D_ + rr];
    }
    __syncthreads();

    int wid = tid >> 5, lane = tid & 31;
    for (int task = wid; task < 48; task += 8) {
        int o   = task / 12;
        int rem = task % 12;
        int h   = rem >> 1;
        int ch  = rem & 1;
        int c   = ch*32 + lane;
        int pp  = o*FIX_ + c*6 + h;
        int g   = pp >> 9;
        const float4* pu4 = (const float4*)pu + (size_t)pp*2;
        float4 pl = __ldg(pu4), ph = __ldg(pu4 + 1);
        float* op = out + ((size_t)(b*H_ + h)*W_ + 4*t0 + o)*C_ + c;
        const float4* zb = (const float4*)(sZ + g*(TT*D_));
#pragma unroll 5
        for (int tl = 0; tl < TT; tl++) {
            float4 zl = zb[tl*2], zh = zb[tl*2 + 1];
            float s0 = zl.x*pl.x, s1 = zl.y*pl.y;
            s0 = fmaf(zl.z, pl.z, s0); s1 = fmaf(zl.w, pl.w, s1);
            s0 = fmaf(zh.x, ph.x, s0); s1 = fmaf(zh.y, ph.y, s1);
            s0 = fmaf(zh.z, ph.z, s0); s1 = fmaf(zh.w, ph.w, s1);
            op[(size_t)tl*4*C_] = s0 + s1;
        }
    }
}

// ---------------------------------------------------------------------------
// K5: final deterministic loss reduction over 1800 partials.
// ---------------------------------------------------------------------------
__global__ void k_final(float* __restrict__ d_out) {
    __shared__ float s[512];
    int tid = threadIdx.x;
    float v = 0.f;
    for (int idx = tid; idx < RVQ_BLOCKS; idx += 512) v += g_partial[idx];
    s[tid] = v; __syncthreads();
    for (int off = 256; off > 0; off >>= 1) {
        if (tid < off) s[tid] += s[tid + off];
        __syncthreads();
    }
    if (tid == 0) {
        float loss = s[0] / (float)(G_ * B_ * T_ * D_);
        d_out[ZQ_SIZE + IDX_SIZE]     = loss;
        d_out[ZQ_SIZE + IDX_SIZE + 1] = loss;
    }
}

// ---------------------------------------------------------------------------
extern "C" void kernel_launch(void* const* d_in, const int* in_sizes, int n_in,
                              void* d_out, int out_size) {
    const float* z_e = (const float*)d_in[0];
    const float* pd  = (const float*)d_in[1];
    const float* pu  = (const float*)d_in[2];
    const float* cb  = (const float*)d_in[3];
    float* out = (float*)d_out;

    cudaFuncSetAttribute(k_down, cudaFuncAttributeMaxDynamicSharedMemorySize, K2_SMEM);

    k_dummy<<<1, 32>>>();   // keeps ncu capture on k_rvq
    k_norm<<<(G_*NVQ_*K_ + 255)/256, 256>>>(cb);
    k_down<<<B_*(T_/8), 256, K2_SMEM>>>(z_e, pd);
    k_rvq<<<RVQ_BLOCKS, 64>>>(out + ZQ_SIZE);
    k_up<<<B_*(T_/TT), 256>>>(pu, out);
    k_final<<<1, 512>>>(out);
}